// round 12
// baseline (speedup 1.0000x reference)
#include <cuda_runtime.h>
#include <cstdint>

#define HID 128
#define ENC_T 8192
#define DEC_T 4096
#define CLUSTER 4
#define TPB 128   // lane = (unit 0..31)<<2 | (gate 0..3)

#define LOG2E 1.4426950408889634f

__device__ __forceinline__ uint32_t smem_u32(const void* p) {
    return (uint32_t)__cvta_generic_to_shared(p);
}

__device__ __forceinline__ uint32_t mapa_(uint32_t laddr, uint32_t rank) {
    uint32_t r;
    asm("mapa.shared::cluster.u32 %0, %1, %2;" : "=r"(r) : "r"(laddr), "r"(rank));
    return r;
}

__device__ __forceinline__ float ex2_(float x) {
    float r;
    asm("ex2.approx.ftz.f32 %0,%1;" : "=f"(r) : "f"(x));
    return r;
}
__device__ __forceinline__ float rcp_(float x) {
    float r;
    asm("rcp.approx.ftz.f32 %0,%1;" : "=f"(r) : "f"(x));
    return r;
}

// 128-term dot: per-lane packed-f32x2 weights vs broadcast h in SMEM.
// a0init is a pre-packed {bias_term, 0} f32x2 accumulator seed.
__device__ __forceinline__ float dot128(const unsigned long long* w2, uint32_t haddr,
                                        unsigned long long a0init) {
    unsigned long long a0 = a0init, a1 = 0ull, a2 = 0ull, a3 = 0ull;
    #pragma unroll
    for (int j = 0; j < 16; j++) {
        unsigned long long h01, h23, h45, h67;
        asm volatile("ld.shared.v2.b64 {%0,%1},[%2];"
                     : "=l"(h01), "=l"(h23) : "r"(haddr + j * 32));
        asm volatile("ld.shared.v2.b64 {%0,%1},[%2];"
                     : "=l"(h45), "=l"(h67) : "r"(haddr + j * 32 + 16));
        asm("fma.rn.f32x2 %0,%1,%2,%0;" : "+l"(a0) : "l"(w2[4 * j + 0]), "l"(h01));
        asm("fma.rn.f32x2 %0,%1,%2,%0;" : "+l"(a1) : "l"(w2[4 * j + 1]), "l"(h23));
        asm("fma.rn.f32x2 %0,%1,%2,%0;" : "+l"(a2) : "l"(w2[4 * j + 2]), "l"(h45));
        asm("fma.rn.f32x2 %0,%1,%2,%0;" : "+l"(a3) : "l"(w2[4 * j + 3]), "l"(h67));
    }
    asm("add.rn.f32x2 %0,%0,%1;" : "+l"(a0) : "l"(a2));
    asm("add.rn.f32x2 %0,%0,%1;" : "+l"(a1) : "l"(a3));
    asm("add.rn.f32x2 %0,%0,%1;" : "+l"(a0) : "l"(a1));
    float lo, hi;
    asm("mov.b64 {%0,%1},%2;" : "=f"(lo), "=f"(hi) : "l"(a0));
    return lo + hi;
}

__device__ __forceinline__ unsigned long long packf2(float lo, float hi) {
    unsigned long long r;
    asm("mov.b64 %0,{%1,%2};" : "=l"(r) : "f"(lo), "f"(hi));
    return r;
}

__global__ void __cluster_dims__(CLUSTER, 1, 1) __launch_bounds__(TPB, 1)
seq2seq_kernel(const float* __restrict__ input_seq,
               const float* __restrict__ enc_Wih, const float* __restrict__ enc_Whh,
               const float* __restrict__ enc_bih, const float* __restrict__ enc_bhh,
               const float* __restrict__ dec_Wih, const float* __restrict__ dec_Whh,
               const float* __restrict__ dec_bih, const float* __restrict__ dec_bhh,
               const float* __restrict__ fc_W,    const float* __restrict__ fc_b,
               float* __restrict__ out)
{
    __shared__ float xs[ENC_T];                               // 32 KB input sequence
    __shared__ __align__(16) float hbuf[2][HID];              // local contiguous h copy (per parity)
    __shared__ __align__(16) unsigned long long pkbuf[2][HID];// {h:f32, tag:s32} delivery slots
    __shared__ float fcW_sm[HID];
    __shared__ float qpart[4];

    const int tid  = threadIdx.x;
    uint32_t rank;
    asm("mov.u32 %0, %%cluster_ctarank;" : "=r"(rank));
    const int unit  = tid >> 2;
    const int gate  = tid & 3;                 // i,f,g,o ; also = delivery-target CTA
    const int gunit = (int)rank * 32 + unit;   // global unit this lane-group owns
    const int row   = gate * HID + gunit;
    const int wid   = tid >> 5;
    const int lane  = tid & 31;
    const unsigned FULL = 0xffffffffu;
    const int base = lane & ~3;
    const bool self_lane = (gate == (int)rank);   // this lane delivers to own CTA

    // Branchless activation constants, log2e prefolded:
    //   sigmoid lanes: a = 1/(1+ex2(-x*log2e))       -> amL=-log2e,  ak=1, ab=0
    //   tanh lane (g): a = 2/(1+ex2(-2x*log2e)) - 1  -> amL=-2log2e, ak=2, ab=-1
    const float amL = (gate == 2) ? -2.0f * LOG2E : -LOG2E;
    const float ak  = (gate == 2) ?  2.0f :  1.0f;
    const float ab  = (gate == 2) ? -1.0f :  0.0f;

    for (int i = tid; i < ENC_T; i += TPB) xs[i] = input_seq[i];
    if (tid < HID) { fcW_sm[tid] = fc_W[tid]; pkbuf[0][tid] = 0ull; pkbuf[1][tid] = 0ull; }
    const float fcb = fc_b[0];

    // hoisted addresses
    const uint32_t hb[2]   = { smem_u32(hbuf[0]), smem_u32(hbuf[1]) };
    const uint32_t pkb[2]  = { smem_u32(pkbuf[0]), smem_u32(pkbuf[1]) };
    const uint32_t slot[2] = { pkb[0] + tid * 8, pkb[1] + tid * 8 };   // my poll slot (unit = tid)
    const uint32_t hloc[2] = { hb[0] + tid * 4, hb[1] + tid * 4 };
    const uint32_t rpk[2]  = { mapa_(pkb[0] + gunit * 8, (uint32_t)gate),
                               mapa_(pkb[1] + gunit * 8, (uint32_t)gate) };
    const uint32_t lpk[2]  = { pkb[0] + gunit * 8, pkb[1] + gunit * 8 };  // local delivery slot

    unsigned long long w2[64];                 // this lane's 128 weights, packed f32x2
    #pragma unroll
    for (int j = 0; j < 64; j++) {
        float a = enc_Whh[row * HID + 2 * j];
        float b = enc_Whh[row * HID + 2 * j + 1];
        asm("mov.b64 %0,{%1,%2};" : "=l"(w2[j]) : "f"(a), "f"(b));
    }
    float btot = enc_bih[row] + enc_bhh[row];
    float wihr = enc_Wih[row];

    float c = 0.0f;                            // cell state (replicated in the 4 gate lanes)

    __syncthreads();
    asm volatile("barrier.cluster.arrive.aligned;" ::: "memory");
    asm volatile("barrier.cluster.wait.aligned;"   ::: "memory");

    // ---------------- encoder: steps s = 0 .. ENC_T-1 ----------------
    #pragma unroll 2
    for (int s = 0; s < ENC_T; ++s) {
        const int p = s & 1, np = p ^ 1;       // compile-time per unrolled copy
        const unsigned long long a0i = packf2(fmaf(wihr, xs[s], btot), 0.0f);

        // single-8B-atomic handshake: tag==s implies h(s) is in the same word
        uint32_t hv; int tg;
        while (true) {
            asm volatile("ld.volatile.shared.v2.b32 {%0,%1},[%2];"
                         : "=r"(hv), "=r"(tg) : "r"(slot[p]));
            if (tg == s) break;
            asm volatile("ld.volatile.shared.v2.b32 {%0,%1},[%2];"
                         : "=r"(hv), "=r"(tg) : "r"(slot[p]));
            if (tg == s) break;
        }
        asm volatile("st.shared.b32 [%0],%1;" :: "r"(hloc[p]), "r"(hv) : "memory");
        __syncthreads();                       // drains STS; all 128 h gathered

        const float acc = dot128(w2, hb[p], a0i);
        const float a  = fmaf(ak, rcp_(ex2_(amL * acc) + 1.0f), ab);
        const float gi = __shfl_sync(FULL, a, base + 0);
        const float gf = __shfl_sync(FULL, a, base + 1);
        const float gg = __shfl_sync(FULL, a, base + 2);
        const float go = __shfl_sync(FULL, a, base + 3);
        c = gf * c + gi * gg;
        const float r2  = rcp_(ex2_((2.0f * LOG2E) * c) + 1.0f);
        const float go2 = go + go;
        const float hn  = fmaf(-go2, r2, go);

        const unsigned long long pkt = packf2(hn, __int_as_float(s + 1));
        // remote deliveries first (3 lanes), local loopback as plain STS (1 lane)
        if (!self_lane)
            asm volatile("st.shared::cluster.b64 [%0],%1;" :: "r"(rpk[np]), "l"(pkt) : "memory");
        else
            asm volatile("st.shared.b64 [%0],%1;" :: "r"(lpk[np]), "l"(pkt) : "memory");
    }

    // ---------------- decoder weights: fold fc_W/fc_b into Whh/bias ----------------
    // W.h + wih*(fcW.h + fcb) + b == (W + wih*fcW^T).h + (b + wih*fcb)
    wihr = dec_Wih[row];
    #pragma unroll
    for (int j = 0; j < 64; j++) {
        float a = fmaf(wihr, fcW_sm[2 * j],     dec_Whh[row * HID + 2 * j]);
        float b = fmaf(wihr, fcW_sm[2 * j + 1], dec_Whh[row * HID + 2 * j + 1]);
        asm("mov.b64 %0,{%1,%2};" : "=l"(w2[j]) : "f"(a), "f"(b));
    }
    const float btot_pl   = dec_bih[row] + dec_bhh[row];
    const float btot_fold = fmaf(wihr, fcb, btot_pl);
    const unsigned long long a0fold = packf2(btot_fold, 0.0f);   // loop-invariant seed

    // fc weights for the out-emitter (rank0 warp0); harmless elsewhere
    const float f0 = fcW_sm[lane], f1 = fcW_sm[lane + 32],
                f2 = fcW_sm[lane + 64], f3 = fcW_sm[lane + 96];
    const bool emitter = (rank == 0) && (wid == 0);

    // ---------------- decoder step d = 0 (peeled: y must be 0) ----------------
    {
        const int s = ENC_T;                   // parity p = 0, np = 1
        uint32_t hv; int tg;
        while (true) {
            asm volatile("ld.volatile.shared.v2.b32 {%0,%1},[%2];"
                         : "=r"(hv), "=r"(tg) : "r"(slot[0]));
            if (tg == s) break;
            asm volatile("ld.volatile.shared.v2.b32 {%0,%1},[%2];"
                         : "=r"(hv), "=r"(tg) : "r"(slot[0]));
            if (tg == s) break;
        }
        asm volatile("st.shared.b32 [%0],%1;" :: "r"(hloc[0]), "r"(hv) : "memory");
        __syncthreads();

        // subtract the folded-in fcW.h_enc term so first step sees y = 0
        float pq = fcW_sm[tid] * hbuf[0][tid];
        #pragma unroll
        for (int o = 1; o < 32; o <<= 1) pq += __shfl_xor_sync(FULL, pq, o);
        if (lane == 0) qpart[wid] = pq;
        __syncthreads();
        const float q = (qpart[0] + qpart[1]) + (qpart[2] + qpart[3]);
        const unsigned long long a0d0 = packf2(btot_pl - wihr * q, 0.0f);

        const float acc = dot128(w2, hb[0], a0d0);
        const float a  = fmaf(ak, rcp_(ex2_(amL * acc) + 1.0f), ab);
        const float gi = __shfl_sync(FULL, a, base + 0);
        const float gf = __shfl_sync(FULL, a, base + 1);
        const float gg = __shfl_sync(FULL, a, base + 2);
        const float go = __shfl_sync(FULL, a, base + 3);
        c = gf * c + gi * gg;
        const float r2  = rcp_(ex2_((2.0f * LOG2E) * c) + 1.0f);
        const float go2 = go + go;
        const float hn  = fmaf(-go2, r2, go);

        const unsigned long long pkt = packf2(hn, __int_as_float(s + 1));
        if (!self_lane)
            asm volatile("st.shared::cluster.b64 [%0],%1;" :: "r"(rpk[1]), "l"(pkt) : "memory");
        else
            asm volatile("st.shared.b64 [%0],%1;" :: "r"(lpk[1]), "l"(pkt) : "memory");
    }

    // ---------------- decoder: steps d = 1 .. DEC_T-1 ----------------
    #pragma unroll 2
    for (int d = 1; d < DEC_T; ++d) {
        const int s = ENC_T + d;
        const int p = s & 1, np = p ^ 1;       // p = d & 1

        uint32_t hv; int tg;
        while (true) {
            asm volatile("ld.volatile.shared.v2.b32 {%0,%1},[%2];"
                         : "=r"(hv), "=r"(tg) : "r"(slot[p]));
            if (tg == s) break;
            asm volatile("ld.volatile.shared.v2.b32 {%0,%1},[%2];"
                         : "=r"(hv), "=r"(tg) : "r"(slot[p]));
            if (tg == s) break;
        }
        asm volatile("st.shared.b32 [%0],%1;" :: "r"(hloc[p]), "r"(hv) : "memory");
        __syncthreads();

        const float acc = dot128(w2, hb[p], a0fold);
        const float a  = fmaf(ak, rcp_(ex2_(amL * acc) + 1.0f), ab);
        const float gi = __shfl_sync(FULL, a, base + 0);
        const float gf = __shfl_sync(FULL, a, base + 1);
        const float gg = __shfl_sync(FULL, a, base + 2);
        const float go = __shfl_sync(FULL, a, base + 3);
        c = gf * c + gi * gg;
        const float r2  = rcp_(ex2_((2.0f * LOG2E) * c) + 1.0f);
        const float go2 = go + go;
        const float hn  = fmaf(-go2, r2, go);

        const unsigned long long pkt = packf2(hn, __int_as_float(s + 1));
        if (!self_lane)
            asm volatile("st.shared::cluster.b64 [%0],%1;" :: "r"(rpk[np]), "l"(pkt) : "memory");
        else
            asm volatile("st.shared.b64 [%0],%1;" :: "r"(lpk[np]), "l"(pkt) : "memory");

        // post-store emission (hidden under next step's DSMEM transit wait):
        // pred_{d-1} = fcW . h(s) + fcb from the local h copy
        if (emitter) {
            float v = f0 * hbuf[p][lane] + f1 * hbuf[p][lane + 32]
                    + f2 * hbuf[p][lane + 64] + f3 * hbuf[p][lane + 96];
            #pragma unroll
            for (int o = 16; o > 0; o >>= 1) v += __shfl_xor_sync(FULL, v, o);
            if (lane == 0) out[d - 1] = v + fcb;
        }
    }

    // final prediction: h(ENC_T+DEC_T) sits in parity-0 slots with tag ENC_T+DEC_T
    if (rank == 0) {
        uint32_t hv; int tg;
        do {
            asm volatile("ld.volatile.shared.v2.b32 {%0,%1},[%2];"
                         : "=r"(hv), "=r"(tg) : "r"(slot[0]));
        } while (tg != ENC_T + DEC_T);
        asm volatile("st.shared.b32 [%0],%1;" :: "r"(hloc[0]), "r"(hv) : "memory");
        __syncthreads();
        if (wid == 0) {
            float v = f0 * hbuf[0][lane] + f1 * hbuf[0][lane + 32]
                    + f2 * hbuf[0][lane + 64] + f3 * hbuf[0][lane + 96];
            #pragma unroll
            for (int o = 16; o > 0; o >>= 1) v += __shfl_xor_sync(FULL, v, o);
            if (lane == 0) out[DEC_T - 1] = v + fcb;
        }
    }

    // keep every CTA alive until all peers' remote stores into our SMEM landed
    asm volatile("barrier.cluster.arrive.aligned;" ::: "memory");
    asm volatile("barrier.cluster.wait.aligned;"   ::: "memory");
}

extern "C" void kernel_launch(void* const* d_in, const int* in_sizes, int n_in,
                              void* d_out, int out_size) {
    (void)in_sizes; (void)n_in; (void)out_size;
    seq2seq_kernel<<<CLUSTER, TPB>>>(
        (const float*)d_in[0],
        (const float*)d_in[1], (const float*)d_in[2],
        (const float*)d_in[3], (const float*)d_in[4],
        (const float*)d_in[5], (const float*)d_in[6],
        (const float*)d_in[7], (const float*)d_in[8],
        (const float*)d_in[9], (const float*)d_in[10],
        (float*)d_out);
}

// round 13
// speedup vs baseline: 1.0223x; 1.0223x over previous
#include <cuda_runtime.h>
#include <cstdint>

#define HID 128
#define ENC_T 8192
#define DEC_T 4096
#define CLUSTER 4
#define TPB 128   // lane = (unit 0..31)<<2 | (gate 0..3)

#define LOG2E 1.4426950408889634f

__device__ __forceinline__ uint32_t smem_u32(const void* p) {
    return (uint32_t)__cvta_generic_to_shared(p);
}

__device__ __forceinline__ uint32_t mapa_(uint32_t laddr, uint32_t rank) {
    uint32_t r;
    asm("mapa.shared::cluster.u32 %0, %1, %2;" : "=r"(r) : "r"(laddr), "r"(rank));
    return r;
}

__device__ __forceinline__ float ex2_(float x) {
    float r;
    asm("ex2.approx.ftz.f32 %0,%1;" : "=f"(r) : "f"(x));
    return r;
}
__device__ __forceinline__ float rcp_(float x) {
    float r;
    asm("rcp.approx.ftz.f32 %0,%1;" : "=f"(r) : "f"(x));
    return r;
}

__device__ __forceinline__ unsigned long long packf2(float lo, float hi) {
    unsigned long long r;
    asm("mov.b64 %0,{%1,%2};" : "=l"(r) : "f"(lo), "f"(hi));
    return r;
}

// 128-term dot: per-lane packed-f32x2 weights vs broadcast h in SMEM.
// a0init is a pre-packed {bias_term, 0} f32x2 accumulator seed.
__device__ __forceinline__ float dot128(const unsigned long long* w2, uint32_t haddr,
                                        unsigned long long a0init) {
    unsigned long long a0 = a0init, a1 = 0ull, a2 = 0ull, a3 = 0ull;
    #pragma unroll
    for (int j = 0; j < 16; j++) {
        unsigned long long h01, h23, h45, h67;
        asm volatile("ld.shared.v2.b64 {%0,%1},[%2];"
                     : "=l"(h01), "=l"(h23) : "r"(haddr + j * 32));
        asm volatile("ld.shared.v2.b64 {%0,%1},[%2];"
                     : "=l"(h45), "=l"(h67) : "r"(haddr + j * 32 + 16));
        asm("fma.rn.f32x2 %0,%1,%2,%0;" : "+l"(a0) : "l"(w2[4 * j + 0]), "l"(h01));
        asm("fma.rn.f32x2 %0,%1,%2,%0;" : "+l"(a1) : "l"(w2[4 * j + 1]), "l"(h23));
        asm("fma.rn.f32x2 %0,%1,%2,%0;" : "+l"(a2) : "l"(w2[4 * j + 2]), "l"(h45));
        asm("fma.rn.f32x2 %0,%1,%2,%0;" : "+l"(a3) : "l"(w2[4 * j + 3]), "l"(h67));
    }
    asm("add.rn.f32x2 %0,%0,%1;" : "+l"(a0) : "l"(a2));
    asm("add.rn.f32x2 %0,%0,%1;" : "+l"(a1) : "l"(a3));
    asm("add.rn.f32x2 %0,%0,%1;" : "+l"(a0) : "l"(a1));
    float lo, hi;
    asm("mov.b64 {%0,%1},%2;" : "=f"(lo), "=f"(hi) : "l"(a0));
    return lo + hi;
}

__global__ void __cluster_dims__(CLUSTER, 1, 1) __launch_bounds__(TPB, 1)
seq2seq_kernel(const float* __restrict__ input_seq,
               const float* __restrict__ enc_Wih, const float* __restrict__ enc_Whh,
               const float* __restrict__ enc_bih, const float* __restrict__ enc_bhh,
               const float* __restrict__ dec_Wih, const float* __restrict__ dec_Whh,
               const float* __restrict__ dec_bih, const float* __restrict__ dec_bhh,
               const float* __restrict__ fc_W,    const float* __restrict__ fc_b,
               float* __restrict__ out)
{
    __shared__ float xs[ENC_T];                               // 32 KB input sequence
    __shared__ __align__(16) float hbuf[2][HID];              // local contiguous h copy (per parity)
    __shared__ __align__(16) unsigned long long pkbuf[2][HID];// {h:f32, tag:s32} delivery slots
    __shared__ float fcW_sm[HID];
    __shared__ float qpart[4];

    const int tid  = threadIdx.x;
    uint32_t rank;
    asm("mov.u32 %0, %%cluster_ctarank;" : "=r"(rank));
    const int unit  = tid >> 2;
    const int gate  = tid & 3;                 // i,f,g,o ; also = delivery-target CTA
    const int gunit = (int)rank * 32 + unit;   // global unit this lane-group owns
    const int row   = gate * HID + gunit;
    const int wid   = tid >> 5;
    const int lane  = tid & 31;
    const unsigned FULL = 0xffffffffu;
    const int base = lane & ~3;

    // Branchless activation constants, log2e prefolded:
    //   sigmoid lanes: a = 1/(1+ex2(-x*log2e))       -> amL=-log2e,  ak=1, ab=0
    //   tanh lane (g): a = 2/(1+ex2(-2x*log2e)) - 1  -> amL=-2log2e, ak=2, ab=-1
    const float amL = (gate == 2) ? -2.0f * LOG2E : -LOG2E;
    const float ak  = (gate == 2) ?  2.0f :  1.0f;
    const float ab  = (gate == 2) ? -1.0f :  0.0f;

    for (int i = tid; i < ENC_T; i += TPB) xs[i] = input_seq[i];
    if (tid < HID) { fcW_sm[tid] = fc_W[tid]; pkbuf[0][tid] = 0ull; pkbuf[1][tid] = 0ull; }
    const float fcb = fc_b[0];

    // hoisted addresses
    const uint32_t hb[2]   = { smem_u32(hbuf[0]), smem_u32(hbuf[1]) };
    const uint32_t pkb[2]  = { smem_u32(pkbuf[0]), smem_u32(pkbuf[1]) };
    const uint32_t slot[2] = { pkb[0] + tid * 8, pkb[1] + tid * 8 };   // my poll slot (unit = tid)
    const uint32_t hloc[2] = { hb[0] + tid * 4, hb[1] + tid * 4 };
    const uint32_t rpk[2]  = { mapa_(pkb[0] + gunit * 8, (uint32_t)gate),
                               mapa_(pkb[1] + gunit * 8, (uint32_t)gate) };

    unsigned long long w2[64];                 // this lane's 128 weights, packed f32x2
    #pragma unroll
    for (int j = 0; j < 64; j++) {
        float a = enc_Whh[row * HID + 2 * j];
        float b = enc_Whh[row * HID + 2 * j + 1];
        asm("mov.b64 %0,{%1,%2};" : "=l"(w2[j]) : "f"(a), "f"(b));
    }
    float btot = enc_bih[row] + enc_bhh[row];
    float wihr = enc_Wih[row];

    float c = 0.0f;                            // cell state (replicated in the 4 gate lanes)

    __syncthreads();
    asm volatile("barrier.cluster.arrive.aligned;" ::: "memory");
    asm volatile("barrier.cluster.wait.aligned;"   ::: "memory");

    // ---------------- encoder: steps s = 0 .. ENC_T-1 ----------------
    #pragma unroll 2
    for (int s = 0; s < ENC_T; ++s) {
        const int p = s & 1, np = p ^ 1;       // compile-time per unrolled copy
        const unsigned long long a0i = packf2(fmaf(wihr, xs[s], btot), 0.0f);

        // single-8B-atomic handshake: tag==s implies h(s) is in the same word
        uint32_t hv; int tg;
        while (true) {
            asm volatile("ld.volatile.shared.v2.b32 {%0,%1},[%2];"
                         : "=r"(hv), "=r"(tg) : "r"(slot[p]));
            if (tg == s) break;
            asm volatile("ld.volatile.shared.v2.b32 {%0,%1},[%2];"
                         : "=r"(hv), "=r"(tg) : "r"(slot[p]));
            if (tg == s) break;
        }
        asm volatile("st.shared.b32 [%0],%1;" :: "r"(hloc[p]), "r"(hv) : "memory");
        __syncthreads();                       // drains STS; all 128 h gathered

        const float acc = dot128(w2, hb[p], a0i);
        const float a  = fmaf(ak, rcp_(ex2_(amL * acc) + 1.0f), ab);
        const float gi = __shfl_sync(FULL, a, base + 0);
        const float gf = __shfl_sync(FULL, a, base + 1);
        const float gg = __shfl_sync(FULL, a, base + 2);
        const float go = __shfl_sync(FULL, a, base + 3);
        c = gf * c + gi * gg;
        const float r2  = rcp_(ex2_((2.0f * LOG2E) * c) + 1.0f);
        const float go2 = go + go;
        const float hn  = fmaf(-go2, r2, go);

        const unsigned long long pkt = packf2(hn, __int_as_float(s + 1));
        asm volatile("st.shared::cluster.b64 [%0],%1;" :: "r"(rpk[np]), "l"(pkt) : "memory");
    }

    // ---------------- decoder weights: fold fc_W/fc_b into Whh/bias ----------------
    // W.h + wih*(fcW.h + fcb) + b == (W + wih*fcW^T).h + (b + wih*fcb)
    wihr = dec_Wih[row];
    #pragma unroll
    for (int j = 0; j < 64; j++) {
        float a = fmaf(wihr, fcW_sm[2 * j],     dec_Whh[row * HID + 2 * j]);
        float b = fmaf(wihr, fcW_sm[2 * j + 1], dec_Whh[row * HID + 2 * j + 1]);
        asm("mov.b64 %0,{%1,%2};" : "=l"(w2[j]) : "f"(a), "f"(b));
    }
    const float btot_pl   = dec_bih[row] + dec_bhh[row];
    const float btot_fold = fmaf(wihr, fcb, btot_pl);
    const unsigned long long a0fold = packf2(btot_fold, 0.0f);   // loop-invariant seed

    // fc weights for the out-emitter (rank0 warp0); harmless elsewhere
    const float f0 = fcW_sm[lane], f1 = fcW_sm[lane + 32],
                f2 = fcW_sm[lane + 64], f3 = fcW_sm[lane + 96];
    const bool emitter = (rank == 0) && (wid == 0);

    // ---------------- decoder step d = 0 (peeled: y must be 0) ----------------
    {
        const int s = ENC_T;                   // parity p = 0, np = 1
        uint32_t hv; int tg;
        while (true) {
            asm volatile("ld.volatile.shared.v2.b32 {%0,%1},[%2];"
                         : "=r"(hv), "=r"(tg) : "r"(slot[0]));
            if (tg == s) break;
            asm volatile("ld.volatile.shared.v2.b32 {%0,%1},[%2];"
                         : "=r"(hv), "=r"(tg) : "r"(slot[0]));
            if (tg == s) break;
        }
        asm volatile("st.shared.b32 [%0],%1;" :: "r"(hloc[0]), "r"(hv) : "memory");
        __syncthreads();

        // subtract the folded-in fcW.h_enc term so the first step sees y = 0
        float pq = fcW_sm[tid] * hbuf[0][tid];
        #pragma unroll
        for (int o = 1; o < 32; o <<= 1) pq += __shfl_xor_sync(FULL, pq, o);
        if (lane == 0) qpart[wid] = pq;
        __syncthreads();
        const float q = (qpart[0] + qpart[1]) + (qpart[2] + qpart[3]);
        const unsigned long long a0d0 = packf2(btot_pl - wihr * q, 0.0f);

        const float acc = dot128(w2, hb[0], a0d0);
        const float a  = fmaf(ak, rcp_(ex2_(amL * acc) + 1.0f), ab);
        const float gi = __shfl_sync(FULL, a, base + 0);
        const float gf = __shfl_sync(FULL, a, base + 1);
        const float gg = __shfl_sync(FULL, a, base + 2);
        const float go = __shfl_sync(FULL, a, base + 3);
        c = gf * c + gi * gg;
        const float r2  = rcp_(ex2_((2.0f * LOG2E) * c) + 1.0f);
        const float go2 = go + go;
        const float hn  = fmaf(-go2, r2, go);

        const unsigned long long pkt = packf2(hn, __int_as_float(s + 1));
        asm volatile("st.shared::cluster.b64 [%0],%1;" :: "r"(rpk[1]), "l"(pkt) : "memory");
    }

    // ---------------- decoder: steps d = 1 .. DEC_T-1 ----------------
    #pragma unroll 2
    for (int d = 1; d < DEC_T; ++d) {
        const int s = ENC_T + d;
        const int p = s & 1, np = p ^ 1;       // p = d & 1

        uint32_t hv; int tg;
        while (true) {
            asm volatile("ld.volatile.shared.v2.b32 {%0,%1},[%2];"
                         : "=r"(hv), "=r"(tg) : "r"(slot[p]));
            if (tg == s) break;
            asm volatile("ld.volatile.shared.v2.b32 {%0,%1},[%2];"
                         : "=r"(hv), "=r"(tg) : "r"(slot[p]));
            if (tg == s) break;
        }
        asm volatile("st.shared.b32 [%0],%1;" :: "r"(hloc[p]), "r"(hv) : "memory");
        __syncthreads();

        const float acc = dot128(w2, hb[p], a0fold);
        const float a  = fmaf(ak, rcp_(ex2_(amL * acc) + 1.0f), ab);
        const float gi = __shfl_sync(FULL, a, base + 0);
        const float gf = __shfl_sync(FULL, a, base + 1);
        const float gg = __shfl_sync(FULL, a, base + 2);
        const float go = __shfl_sync(FULL, a, base + 3);
        c = gf * c + gi * gg;
        const float r2  = rcp_(ex2_((2.0f * LOG2E) * c) + 1.0f);
        const float go2 = go + go;
        const float hn  = fmaf(-go2, r2, go);

        const unsigned long long pkt = packf2(hn, __int_as_float(s + 1));
        asm volatile("st.shared::cluster.b64 [%0],%1;" :: "r"(rpk[np]), "l"(pkt) : "memory");

        // post-store emission (hidden under next step's DSMEM transit wait):
        // pred_{d-1} = fcW . h(s) + fcb from the local h copy
        if (emitter) {
            float v = f0 * hbuf[p][lane] + f1 * hbuf[p][lane + 32]
                    + f2 * hbuf[p][lane + 64] + f3 * hbuf[p][lane + 96];
            #pragma unroll
            for (int o = 16; o > 0; o >>= 1) v += __shfl_xor_sync(FULL, v, o);
            if (lane == 0) out[d - 1] = v + fcb;
        }
    }

    // final prediction: h(ENC_T+DEC_T) sits in parity-0 slots with tag ENC_T+DEC_T
    if (rank == 0) {
        uint32_t hv; int tg;
        do {
            asm volatile("ld.volatile.shared.v2.b32 {%0,%1},[%2];"
                         : "=r"(hv), "=r"(tg) : "r"(slot[0]));
        } while (tg != ENC_T + DEC_T);
        asm volatile("st.shared.b32 [%0],%1;" :: "r"(hloc[0]), "r"(hv) : "memory");
        __syncthreads();
        if (wid == 0) {
            float v = f0 * hbuf[0][lane] + f1 * hbuf[0][lane + 32]
                    + f2 * hbuf[0][lane + 64] + f3 * hbuf[0][lane + 96];
            #pragma unroll
            for (int o = 16; o > 0; o >>= 1) v += __shfl_xor_sync(FULL, v, o);
            if (lane == 0) out[DEC_T - 1] = v + fcb;
        }
    }

    // keep every CTA alive until all peers' remote stores into our SMEM landed
    asm volatile("barrier.cluster.arrive.aligned;" ::: "memory");
    asm volatile("barrier.cluster.wait.aligned;"   ::: "memory");
}

extern "C" void kernel_launch(void* const* d_in, const int* in_sizes, int n_in,
                              void* d_out, int out_size) {
    (void)in_sizes; (void)n_in; (void)out_size;
    seq2seq_kernel<<<CLUSTER, TPB>>>(
        (const float*)d_in[0],
        (const float*)d_in[1], (const float*)d_in[2],
        (const float*)d_in[3], (const float*)d_in[4],
        (const float*)d_in[5], (const float*)d_in[6],
        (const float*)d_in[7], (const float*)d_in[8],
        (const float*)d_in[9], (const float*)d_in[10],
        (float*)d_out);
}